// round 10
// baseline (speedup 1.0000x reference)
#include <cuda_runtime.h>
#include <cstdint>

// Problem dims (fixed by the reference)
#define BB 4096   // batch
#define DD 1024   // input dim
#define HH 4096   // hidden dim
#define OO 1000   // output dim

// Eigen-master aarch64 GEBP blocking: mr=12, nr=8, l1 default 16KB:
//   kc = ((16384 - 12*8*4) / (12*4 + 8*4)) rounded to kr=8  ->  200
#define KC 200

typedef unsigned long long u64;

// amax slots: 0=x 1=W0 2=W1 3=W2 4=h1 5=h2
__device__ unsigned g_stats[8];

// int8 quantized tensors + fp32 hidden activations
__device__ int8_t g_qx [BB * DD];
__device__ int8_t g_qw0[HH * DD];
__device__ int8_t g_qw1[HH * HH];
__device__ int8_t g_qw2[OO * HH];
__device__ float  g_h  [BB * HH];
__device__ int8_t g_qh [BB * HH];

__global__ void k_init() {
    if (threadIdx.x < 8) g_stats[threadIdx.x] = 0u;
}

// ---------------------------------------------------------------------------
// absmax (exact, order-independent)
// ---------------------------------------------------------------------------
__global__ void k_absmax(const float4* __restrict__ t, int n4, int idx) {
    float m = 0.f;
    for (int i = blockIdx.x * blockDim.x + threadIdx.x; i < n4;
         i += gridDim.x * blockDim.x) {
        float4 v = t[i];
        m = fmaxf(m, fmaxf(fmaxf(fabsf(v.x), fabsf(v.y)),
                           fmaxf(fabsf(v.z), fabsf(v.w))));
    }
#pragma unroll
    for (int o = 16; o; o >>= 1)
        m = fmaxf(m, __shfl_xor_sync(0xffffffffu, m, o));
    if ((threadIdx.x & 31) == 0)
        atomicMax(&g_stats[idx], __float_as_uint(m));
}

// ---------------------------------------------------------------------------
// quantize: q = clip(round_half_even(fl(t / scale)), -4, 3)  (ref op-for-op)
// ---------------------------------------------------------------------------
__global__ void k_quant(const float4* __restrict__ t, char4* __restrict__ q,
                        int n4, int idx) {
    const float amax  = __uint_as_float(g_stats[idx]);
    const float scale = fmaxf(__fdiv_rn(amax, 3.0f), 1e-8f);
    for (int i = blockIdx.x * blockDim.x + threadIdx.x; i < n4;
         i += gridDim.x * blockDim.x) {
        float4 v = t[i];
        int a = (int)fminf(fmaxf(rintf(__fdiv_rn(v.x, scale)), -4.f), 3.f);
        int b = (int)fminf(fmaxf(rintf(__fdiv_rn(v.y, scale)), -4.f), 3.f);
        int c = (int)fminf(fmaxf(rintf(__fdiv_rn(v.z, scale)), -4.f), 3.f);
        int d = (int)fminf(fmaxf(rintf(__fdiv_rn(v.w, scale)), -4.f), 3.f);
        q[i] = make_char4((signed char)a, (signed char)b,
                          (signed char)c, (signed char)d);
    }
}

// ---------------------------------------------------------------------------
// packed f32x2 helpers: two INDEPENDENT lane-wise fp32 ops per instruction.
// Per-lane arithmetic is bitwise identical to scalar fp32 FMA/ADD chains.
// ---------------------------------------------------------------------------
__device__ __forceinline__ u64 pk2(float lo, float hi) {
    u64 r; asm("mov.b64 %0, {%1, %2};" : "=l"(r) : "f"(lo), "f"(hi)); return r;
}
__device__ __forceinline__ void upk2(u64 v, float& lo, float& hi) {
    asm("mov.b64 {%0, %1}, %2;" : "=f"(lo), "=f"(hi) : "l"(v));
}
__device__ __forceinline__ u64 ffma2(u64 a, u64 b, u64 c) {
    u64 r; asm("fma.rn.f32x2 %0, %1, %2, %3;" : "=l"(r) : "l"(a), "l"(b), "l"(c));
    return r;
}
__device__ __forceinline__ u64 fadd2(u64 a, u64 b) {
    u64 r; asm("add.rn.f32x2 %0, %1, %2;" : "=l"(r) : "l"(a), "l"(b));
    return r;
}

// ---------------------------------------------------------------------------
// Eigen-replica fp32 GEMM:  C[M,N] = A[M,K] @ B[N,K]^T (+bias, +ReLU)
// Per output element, Eigen (master, aarch64) contraction arithmetic:
//   - fused fp32 FMA chains, ascending k within panels of KC=200 (acc = 0)
//   - panels folded sequentially:  C = fl(S_p + C)
//   - then fl(C + bias), optional ReLU
// Operands dequantized on the fly: value = fl(q * scale) (bitwise = ref's
// fake-quant outputs). Fused absmax of the stored output.
// ---------------------------------------------------------------------------
__global__ __launch_bounds__(256, 1) void k_gemm_eig(
    const int8_t* __restrict__ A, const int8_t* __restrict__ Bw,
    const float* __restrict__ bias, float* __restrict__ C,
    int M, int N, int K, int ia, int ib, int relu, int iamax)
{
    __shared__ u64   sA [8 * 128];   // [k][m], value duplicated {v,v}
    __shared__ float sBf[8 * 128];   // [k][slot], interleaved for LDS.64

    const int tid = threadIdx.x;
    const int tx  = tid & 15;         // 16 col groups (8 cols each)
    const int ty  = tid >> 4;         // 16 row groups (8 rows each)
    const int bm  = blockIdx.y * 128;
    const int bn  = blockIdx.x * 128;
    const int lr  = tid >> 1;         // loader row 0..127
    const int lc  = (tid & 1) * 4;    // loader k-col base {0,4}

    const float sa = fmaxf(__fdiv_rn(__uint_as_float(g_stats[ia]), 3.0f), 1e-8f);
    const float sb = fmaxf(__fdiv_rn(__uint_as_float(g_stats[ib]), 3.0f), 1e-8f);

    // float-slot for B element (k, n_local=lr): pair p=lr>>1 -> u64 slot
    // (p&3)*16+(p>>2), half = lr&1
    const int sslotf = ((lr >> 1) & 3) * 32 + (lr >> 3) * 2 + (lr & 1);

    u64 S[8][4], Cc[8][4];
#pragma unroll
    for (int i = 0; i < 8; i++)
#pragma unroll
        for (int j = 0; j < 4; j++) { S[i][j] = 0ull; Cc[i][j] = 0ull; }

    for (int k0 = 0; k0 < K; k0 += 8) {
        if (k0 && (k0 % KC == 0)) {   // Eigen panel boundary: C = fl(S + C)
#pragma unroll
            for (int i = 0; i < 8; i++)
#pragma unroll
                for (int j = 0; j < 4; j++) {
                    Cc[i][j] = fadd2(S[i][j], Cc[i][j]);
                    S[i][j]  = 0ull;
                }
        }
        {   // A tile: dequant fl(q*sa)
            char4 a4 = *reinterpret_cast<const char4*>(
                A + (size_t)(bm + lr) * K + k0 + lc);
            float av[4] = {__fmul_rn((float)a4.x, sa), __fmul_rn((float)a4.y, sa),
                           __fmul_rn((float)a4.z, sa), __fmul_rn((float)a4.w, sa)};
#pragma unroll
            for (int j = 0; j < 4; j++)
                sA[(lc + j) * 128 + lr] = pk2(av[j], av[j]);
        }
        {   // B tile: dequant fl(q*sb); rows >= N -> 0 (chain-neutral)
            char4 b4 = make_char4(0, 0, 0, 0);
            if (bn + lr < N)
                b4 = *reinterpret_cast<const char4*>(
                    Bw + (size_t)(bn + lr) * K + k0 + lc);
            float bv[4] = {__fmul_rn((float)b4.x, sb), __fmul_rn((float)b4.y, sb),
                           __fmul_rn((float)b4.z, sb), __fmul_rn((float)b4.w, sb)};
#pragma unroll
            for (int j = 0; j < 4; j++)
                sBf[(lc + j) * 128 + sslotf] = bv[j];
        }
        __syncthreads();

        const u64* sBu = reinterpret_cast<const u64*>(sBf);
#pragma unroll
        for (int kk = 0; kk < 8; kk++) {          // ascending k within panel
            u64 b2[4];
#pragma unroll
            for (int j = 0; j < 4; j++)
                b2[j] = sBu[kk * 64 + j * 16 + tx];
#pragma unroll
            for (int i = 0; i < 8; i++) {
                u64 a2 = sA[kk * 128 + ty * 8 + i];
#pragma unroll
                for (int j = 0; j < 4; j++)
                    S[i][j] = ffma2(a2, b2[j], S[i][j]);
            }
        }
        __syncthreads();
    }

    // final panel fold
#pragma unroll
    for (int i = 0; i < 8; i++)
#pragma unroll
        for (int j = 0; j < 4; j++)
            Cc[i][j] = fadd2(S[i][j], Cc[i][j]);

    // Epilogue: fl(C + bias), optional ReLU, store, fused absmax
    float lmax = 0.f;
#pragma unroll
    for (int i = 0; i < 8; i++) {
        const int row = bm + ty * 8 + i;
#pragma unroll
        for (int j = 0; j < 4; j++) {
            float y0, y1;
            upk2(Cc[i][j], y0, y1);
            const int c0 = bn + tx * 8 + j * 2;
            if (c0 < N) {
                float y = __fadd_rn(y0, bias[c0]);
                if (relu) y = fmaxf(y, 0.f);
                C[(size_t)row * N + c0] = y;
                lmax = fmaxf(lmax, fabsf(y));
            }
            if (c0 + 1 < N) {
                float y = __fadd_rn(y1, bias[c0 + 1]);
                if (relu) y = fmaxf(y, 0.f);
                C[(size_t)row * N + c0 + 1] = y;
                lmax = fmaxf(lmax, fabsf(y));
            }
        }
    }
    if (iamax >= 0) {
#pragma unroll
        for (int o = 16; o; o >>= 1)
            lmax = fmaxf(lmax, __shfl_xor_sync(0xffffffffu, lmax, o));
        if ((tid & 31) == 0)
            atomicMax(&g_stats[iamax], __float_as_uint(lmax));
    }
}

// ---------------------------------------------------------------------------
extern "C" void kernel_launch(void* const* d_in, const int* in_sizes, int n_in,
                              void* d_out, int out_size) {
    const float* x  = (const float*)d_in[0];
    const float* W0 = (const float*)d_in[1];
    const float* b0 = (const float*)d_in[2];
    const float* W1 = (const float*)d_in[3];
    const float* b1 = (const float*)d_in[4];
    const float* W2 = (const float*)d_in[5];
    const float* b2 = (const float*)d_in[6];
    float* out = (float*)d_out;

    void *p_qx, *p_qw0, *p_qw1, *p_qw2, *p_h, *p_qh;
    cudaGetSymbolAddress(&p_qx,  g_qx);
    cudaGetSymbolAddress(&p_qw0, g_qw0);
    cudaGetSymbolAddress(&p_qw1, g_qw1);
    cudaGetSymbolAddress(&p_qw2, g_qw2);
    cudaGetSymbolAddress(&p_h,   g_h);
    cudaGetSymbolAddress(&p_qh,  g_qh);

    k_init<<<1, 32>>>();

    k_absmax<<<1024, 256>>>((const float4*)x,  (BB * DD) / 4, 0);
    k_absmax<<<1024, 256>>>((const float4*)W0, (HH * DD) / 4, 1);
    k_absmax<<<2048, 256>>>((const float4*)W1, (HH * HH) / 4, 2);
    k_absmax<<<1024, 256>>>((const float4*)W2, (OO * HH) / 4, 3);

    k_quant<<<1024, 256>>>((const float4*)x,  (char4*)p_qx,  (BB * DD) / 4, 0);
    k_quant<<<1024, 256>>>((const float4*)W0, (char4*)p_qw0, (HH * DD) / 4, 1);
    k_quant<<<2048, 256>>>((const float4*)W1, (char4*)p_qw1, (HH * HH) / 4, 2);
    k_quant<<<1024, 256>>>((const float4*)W2, (char4*)p_qw2, (OO * HH) / 4, 3);

    dim3 blk(256);
    dim3 g01(HH / 128, BB / 128);            // 32 x 32
    dim3 g2((OO + 127) / 128, BB / 128);     // 8 x 32

    // Layer 0: h = relu(fq(x) @ fq(W0)^T + b0), fused absmax -> slot 4
    k_gemm_eig<<<g01, blk>>>((const int8_t*)p_qx, (const int8_t*)p_qw0, b0,
                             (float*)p_h, BB, HH, DD, 0, 1, 1, 4);
    k_quant<<<2048, 256>>>((const float4*)p_h, (char4*)p_qh, (BB * HH) / 4, 4);

    // Layer 1: h = relu(fq(h) @ fq(W1)^T + b1), fused absmax -> slot 5
    k_gemm_eig<<<g01, blk>>>((const int8_t*)p_qh, (const int8_t*)p_qw1, b1,
                             (float*)p_h, BB, HH, HH, 4, 2, 1, 5);
    k_quant<<<2048, 256>>>((const float4*)p_h, (char4*)p_qh, (BB * HH) / 4, 5);

    // Layer 2: out = fq(h) @ fq(W2)^T + b2 (no relu, no further quant)
    k_gemm_eig<<<g2, blk>>>((const int8_t*)p_qh, (const int8_t*)p_qw2, b2,
                            out, BB, OO, HH, 5, 3, 0, -1);
}

// round 12
// speedup vs baseline: 1.2591x; 1.2591x over previous
#include <cuda_runtime.h>
#include <cstdint>

// Problem dims (fixed by the reference)
#define BB 4096   // batch
#define DD 1024   // input dim
#define HH 4096   // hidden dim
#define OO 1000   // output dim

// Eigen-master aarch64 GEBP blocking: kc = 200 (VERIFIED: passes at 9.54e-4)
#define KC 200
#define TK 16     // k-slab per smem stage (KC % 8 == 0; folds land on 8-grid)

typedef unsigned long long u64;

// amax slots: 0=x 1=W0 2=W1 3=W2 4=h1 5=h2
__device__ unsigned g_stats[8];

// int8 quantized tensors + fp32 hidden activations
__device__ int8_t g_qx [BB * DD];
__device__ int8_t g_qw0[HH * DD];
__device__ int8_t g_qw1[HH * HH];
__device__ int8_t g_qw2[OO * HH];
__device__ float  g_h  [BB * HH];
__device__ int8_t g_qh [BB * HH];

__global__ void k_init() {
    if (threadIdx.x < 8) g_stats[threadIdx.x] = 0u;
}

// ---------------------------------------------------------------------------
// absmax (exact, order-independent)
// ---------------------------------------------------------------------------
__global__ void k_absmax(const float4* __restrict__ t, int n4, int idx) {
    float m = 0.f;
    for (int i = blockIdx.x * blockDim.x + threadIdx.x; i < n4;
         i += gridDim.x * blockDim.x) {
        float4 v = t[i];
        m = fmaxf(m, fmaxf(fmaxf(fabsf(v.x), fabsf(v.y)),
                           fmaxf(fabsf(v.z), fabsf(v.w))));
    }
#pragma unroll
    for (int o = 16; o; o >>= 1)
        m = fmaxf(m, __shfl_xor_sync(0xffffffffu, m, o));
    if ((threadIdx.x & 31) == 0)
        atomicMax(&g_stats[idx], __float_as_uint(m));
}

// ---------------------------------------------------------------------------
// quantize: q = clip(round_half_even(fl(t / scale)), -4, 3)  (ref op-for-op)
// ---------------------------------------------------------------------------
__global__ void k_quant(const float4* __restrict__ t, char4* __restrict__ q,
                        int n4, int idx) {
    const float amax  = __uint_as_float(g_stats[idx]);
    const float scale = fmaxf(__fdiv_rn(amax, 3.0f), 1e-8f);
    for (int i = blockIdx.x * blockDim.x + threadIdx.x; i < n4;
         i += gridDim.x * blockDim.x) {
        float4 v = t[i];
        int a = (int)fminf(fmaxf(rintf(__fdiv_rn(v.x, scale)), -4.f), 3.f);
        int b = (int)fminf(fmaxf(rintf(__fdiv_rn(v.y, scale)), -4.f), 3.f);
        int c = (int)fminf(fmaxf(rintf(__fdiv_rn(v.z, scale)), -4.f), 3.f);
        int d = (int)fminf(fmaxf(rintf(__fdiv_rn(v.w, scale)), -4.f), 3.f);
        q[i] = make_char4((signed char)a, (signed char)b,
                          (signed char)c, (signed char)d);
    }
}

// ---------------------------------------------------------------------------
// packed f32x2 helpers: two INDEPENDENT lane-wise fp32 ops per instruction.
// Per-lane arithmetic is bitwise identical to scalar fp32 FMA/ADD chains.
// ---------------------------------------------------------------------------
__device__ __forceinline__ u64 pk2(float lo, float hi) {
    u64 r; asm("mov.b64 %0, {%1, %2};" : "=l"(r) : "f"(lo), "f"(hi)); return r;
}
__device__ __forceinline__ void upk2(u64 v, float& lo, float& hi) {
    asm("mov.b64 {%0, %1}, %2;" : "=f"(lo), "=f"(hi) : "l"(v));
}
__device__ __forceinline__ u64 ffma2(u64 a, u64 b, u64 c) {
    u64 r; asm("fma.rn.f32x2 %0, %1, %2, %3;" : "=l"(r) : "l"(a), "l"(b), "l"(c));
    return r;
}
__device__ __forceinline__ u64 fadd2(u64 a, u64 b) {
    u64 r; asm("add.rn.f32x2 %0, %1, %2;" : "=l"(r) : "l"(a), "l"(b));
    return r;
}

// ---------------------------------------------------------------------------
// Eigen-replica fp32 GEMM (v2: double-buffered, balanced smem traffic).
// Arithmetic per output element is BITWISE IDENTICAL to the R10 kernel:
//   fused fp32 FMA chain, ascending k, panels of KC=200 folded C = fl(S+C),
//   then fl(C+bias), optional ReLU. Operands fl(q*scale). Fused absmax.
// ---------------------------------------------------------------------------
__global__ __launch_bounds__(256, 1) void k_gemm_eig(
    const int8_t* __restrict__ A, const int8_t* __restrict__ Bw,
    const float* __restrict__ bias, float* __restrict__ C,
    int M, int N, int K, int ia, int ib, int relu, int iamax)
{
    __shared__ float sA[2][TK][128];   // [buf][k][m] plain floats
    __shared__ float sB[2][TK][128];   // [buf][k][n] plain floats

    const int tid = threadIdx.x;
    const int tx  = tid & 15;          // 16 col groups (8 cols each)
    const int ty  = tid >> 4;          // 16 row groups (8 rows each)
    const int bm  = blockIdx.y * 128;
    const int bn  = blockIdx.x * 128;
    const int lr  = tid >> 1;          // loader row 0..127
    const int lkb = (tid & 1) * 8;     // loader k base {0,8}

    const float sa = fmaxf(__fdiv_rn(__uint_as_float(g_stats[ia]), 3.0f), 1e-8f);
    const float sb = fmaxf(__fdiv_rn(__uint_as_float(g_stats[ib]), 3.0f), 1e-8f);

    const int8_t* Ab = A + (size_t)(bm + lr) * K + lkb;
    const bool bok   = (bn + lr) < N;
    const int8_t* Bb = Bw + (size_t)(bok ? (bn + lr) : 0) * K + lkb;

#define STAGE(b, ra, rb) do {                                                  \
    _Pragma("unroll")                                                          \
    for (int j = 0; j < 8; j++) {                                              \
        float fa = __fmul_rn((float)(signed char)((ra) >> (8 * j)), sa);       \
        float fb = __fmul_rn((float)(signed char)((rb) >> (8 * j)), sb);       \
        sA[b][lkb + j][lr] = fa;                                               \
        sB[b][lkb + j][lr] = fb;                                               \
    } } while (0)

#define FOLD() do {                                                            \
    _Pragma("unroll")                                                          \
    for (int i = 0; i < 8; i++)                                                \
        _Pragma("unroll")                                                      \
        for (int j = 0; j < 4; j++) {                                          \
            Cc[i][j] = fadd2(S[i][j], Cc[i][j]);                               \
            S[i][j]  = 0ull;                                                   \
        } } while (0)

#define BLOCK(b, o) do {                                                       \
    _Pragma("unroll")                                                          \
    for (int kk = (o); kk < (o) + 8; kk++) {                                   \
        const float4 a0 = *reinterpret_cast<const float4*>(                    \
            &sA[b][kk][ty * 8]);                                               \
        const float4 a1 = *reinterpret_cast<const float4*>(                    \
            &sA[b][kk][ty * 8 + 4]);                                           \
        const ulonglong2 q0 = *reinterpret_cast<const ulonglong2*>(            \
            &sB[b][kk][tx * 8]);                                               \
        const ulonglong2 q1 = *reinterpret_cast<const ulonglong2*>(            \
            &sB[b][kk][tx * 8 + 4]);                                           \
        u64 b2[4] = {q0.x, q0.y, q1.x, q1.y};                                  \
        float av[8] = {a0.x, a0.y, a0.z, a0.w, a1.x, a1.y, a1.z, a1.w};        \
        _Pragma("unroll")                                                      \
        for (int i = 0; i < 8; i++) {                                          \
            u64 a2 = pk2(av[i], av[i]);                                        \
            _Pragma("unroll")                                                  \
            for (int j = 0; j < 4; j++)                                        \
                S[i][j] = ffma2(a2, b2[j], S[i][j]);                           \
        } } } while (0)

    u64 S[8][4], Cc[8][4];
#pragma unroll
    for (int i = 0; i < 8; i++)
#pragma unroll
        for (int j = 0; j < 4; j++) { S[i][j] = 0ull; Cc[i][j] = 0ull; }

    // prologue: stage slab 0
    {
        u64 ra = *reinterpret_cast<const u64*>(Ab);
        u64 rb = bok ? *reinterpret_cast<const u64*>(Bb) : 0ull;
        STAGE(0, ra, rb);
    }
    __syncthreads();

    int buf = 0;
    for (int k0 = 0; k0 < K; k0 += TK) {
        // issue next slab's gmem loads (latency hidden by BLOCKs below)
        u64 ra = 0ull, rb = 0ull;
        const bool more = (k0 + TK) < K;
        if (more) {
            ra = *reinterpret_cast<const u64*>(Ab + k0 + TK);
            rb = bok ? *reinterpret_cast<const u64*>(Bb + k0 + TK) : 0ull;
        }

        if (k0 && (k0 % KC == 0)) FOLD();
        BLOCK(buf, 0);
        if (((k0 + 8) % KC) == 0) FOLD();
        BLOCK(buf, 8);

        if (more) STAGE(buf ^ 1, ra, rb);
        __syncthreads();
        buf ^= 1;
    }
    FOLD();   // final panel

    // Epilogue: fl(C + bias), optional ReLU, store, fused absmax
    float lmax = 0.f;
#pragma unroll
    for (int i = 0; i < 8; i++) {
        const int row = bm + ty * 8 + i;
#pragma unroll
        for (int j = 0; j < 4; j++) {
            float y0, y1;
            upk2(Cc[i][j], y0, y1);
            const int c0 = bn + tx * 8 + j * 2;
            if (c0 < N) {
                float y = __fadd_rn(y0, bias[c0]);
                if (relu) y = fmaxf(y, 0.f);
                C[(size_t)row * N + c0] = y;
                lmax = fmaxf(lmax, fabsf(y));
            }
            if (c0 + 1 < N) {
                float y = __fadd_rn(y1, bias[c0 + 1]);
                if (relu) y = fmaxf(y, 0.f);
                C[(size_t)row * N + c0 + 1] = y;
                lmax = fmaxf(lmax, fabsf(y));
            }
        }
    }
    if (iamax >= 0) {
#pragma unroll
        for (int o = 16; o; o >>= 1)
            lmax = fmaxf(lmax, __shfl_xor_sync(0xffffffffu, lmax, o));
        if ((tid & 31) == 0)
            atomicMax(&g_stats[iamax], __float_as_uint(lmax));
    }
#undef STAGE
#undef FOLD
#undef BLOCK
}

// ---------------------------------------------------------------------------
extern "C" void kernel_launch(void* const* d_in, const int* in_sizes, int n_in,
                              void* d_out, int out_size) {
    const float* x  = (const float*)d_in[0];
    const float* W0 = (const float*)d_in[1];
    const float* b0 = (const float*)d_in[2];
    const float* W1 = (const float*)d_in[3];
    const float* b1 = (const float*)d_in[4];
    const float* W2 = (const float*)d_in[5];
    const float* b2 = (const float*)d_in[6];
    float* out = (float*)d_out;

    void *p_qx, *p_qw0, *p_qw1, *p_qw2, *p_h, *p_qh;
    cudaGetSymbolAddress(&p_qx,  g_qx);
    cudaGetSymbolAddress(&p_qw0, g_qw0);
    cudaGetSymbolAddress(&p_qw1, g_qw1);
    cudaGetSymbolAddress(&p_qw2, g_qw2);
    cudaGetSymbolAddress(&p_h,   g_h);
    cudaGetSymbolAddress(&p_qh,  g_qh);

    k_init<<<1, 32>>>();

    k_absmax<<<1024, 256>>>((const float4*)x,  (BB * DD) / 4, 0);
    k_absmax<<<1024, 256>>>((const float4*)W0, (HH * DD) / 4, 1);
    k_absmax<<<2048, 256>>>((const float4*)W1, (HH * HH) / 4, 2);
    k_absmax<<<1024, 256>>>((const float4*)W2, (OO * HH) / 4, 3);

    k_quant<<<1024, 256>>>((const float4*)x,  (char4*)p_qx,  (BB * DD) / 4, 0);
    k_quant<<<1024, 256>>>((const float4*)W0, (char4*)p_qw0, (HH * DD) / 4, 1);
    k_quant<<<2048, 256>>>((const float4*)W1, (char4*)p_qw1, (HH * HH) / 4, 2);
    k_quant<<<1024, 256>>>((const float4*)W2, (char4*)p_qw2, (OO * HH) / 4, 3);

    dim3 blk(256);
    dim3 g01(HH / 128, BB / 128);            // 32 x 32
    dim3 g2((OO + 127) / 128, BB / 128);     // 8 x 32

    // Layer 0: h = relu(fq(x) @ fq(W0)^T + b0), fused absmax -> slot 4
    k_gemm_eig<<<g01, blk>>>((const int8_t*)p_qx, (const int8_t*)p_qw0, b0,
                             (float*)p_h, BB, HH, DD, 0, 1, 1, 4);
    k_quant<<<2048, 256>>>((const float4*)p_h, (char4*)p_qh, (BB * HH) / 4, 4);

    // Layer 1: h = relu(fq(h) @ fq(W1)^T + b1), fused absmax -> slot 5
    k_gemm_eig<<<g01, blk>>>((const int8_t*)p_qh, (const int8_t*)p_qw1, b1,
                             (float*)p_h, BB, HH, HH, 4, 2, 1, 5);
    k_quant<<<2048, 256>>>((const float4*)p_h, (char4*)p_qh, (BB * HH) / 4, 5);

    // Layer 2: out = fq(h) @ fq(W2)^T + b2 (no relu, no further quant)
    k_gemm_eig<<<g2, blk>>>((const int8_t*)p_qh, (const int8_t*)p_qw2, b2,
                            out, BB, OO, HH, 5, 3, 0, -1);
}